// round 1
// baseline (speedup 1.0000x reference)
#include <cuda_runtime.h>
#include <math.h>

#define ROW 85          // 5 + NUM_CLASSES
#define NCLS 80
#define NB 1024
#define NT 256
#define MAXT 4096       // max B*T supported
#define LOG_CLAMP -100.0f

__device__ float g_partials[NB];

__device__ __forceinline__ float sigm(float x) {
    return 1.0f / (1.0f + expf(-x));
}
// matches reference: max(log(s), -100) with log(0) -> -inf -> -100
__device__ __forceinline__ float clog(float s) {
    return fmaxf(logf(s), LOG_CLAMP);
}
// decode H/W whether stored as int32 (or low word of int64) or float32 bits
__device__ __forceinline__ int decode_dim(const int* p) {
    int raw = p[0];
    if (raw >= (1 << 20) || raw < 0) {            // looks like float bit pattern
        return (int)__int_as_float(raw);
    }
    return raw;
}

// Kernel 1: dense part of conf BCE assuming obj_mask == 0 everywhere.
// base = sum over all cells of -clamp(log(1 - sigmoid(p4)))
__global__ void conf_base_kernel(const float* __restrict__ pred, long n_cells) {
    __shared__ float sh[NT];
    float acc = 0.0f;
    for (long i = (long)blockIdx.x * NT + threadIdx.x; i < n_cells;
         i += (long)NB * NT) {
        float x = __ldg(&pred[i * ROW + 4]);
        float s = sigm(x);
        acc += -clog(1.0f - s);
    }
    sh[threadIdx.x] = acc;
    __syncthreads();
    for (int o = NT / 2; o > 0; o >>= 1) {
        if (threadIdx.x < o) sh[threadIdx.x] += sh[threadIdx.x + o];
        __syncthreads();
    }
    if (threadIdx.x == 0) g_partials[blockIdx.x] = sh[0];
}

// Kernel 2 (single block): gathered losses + conf correction + final combine.
__global__ void finish_kernel(const float* __restrict__ pred,
                              const float* __restrict__ tgt,
                              const int* __restrict__ Hp,
                              const int* __restrict__ Wp,
                              long n_pred, long n_tgt,
                              float* __restrict__ out, int out_size) {
    const int H = decode_dim(Hp);
    const int W = decode_dim(Wp);
    const long HW = (long)H * (long)W;
    const int B = (int)(n_pred / (HW * ROW));
    const int T = (int)(n_tgt / (5L * B));
    const int NTG = B * T;

    __shared__ int s_gi[MAXT];
    __shared__ unsigned char s_valid[MAXT];
    __shared__ float sh[NT];

    const float fW = (float)W, fH = (float)H;

    // ---- pass 1: valid + cell index per target ----
    for (int t = threadIdx.x; t < NTG; t += blockDim.x) {
        const float* tg = tgt + (long)t * 5;
        float cid = tg[0], cx = tg[1], cy = tg[2], w = tg[3], h = tg[4];
        bool fin = isfinite(cid) && isfinite(cx) && isfinite(cy) &&
                   isfinite(w) && isfinite(h);
        float gx = floorf(cx * fW);
        float gy = floorf(cy * fH);
        bool v = fin && (gx >= 0.0f) && (gx < fW) && (gy >= 0.0f) && (gy < fH);
        float gxc = fminf(fmaxf(gx, 0.0f), fW - 1.0f);
        float gyc = fminf(fmaxf(gy, 0.0f), fH - 1.0f);
        // NaN -> fmax/fmin propagate the non-NaN operand -> clipped to range
        if (!(gxc == gxc)) gxc = 0.0f;
        if (!(gyc == gyc)) gyc = 0.0f;
        int gi = (int)gyc * W + (int)gxc;
        s_gi[t] = gi;
        s_valid[t] = v ? 1 : 0;
    }
    __syncthreads();

    // ---- pass 2: gathered losses + unique-cell conf correction ----
    float a_xy = 0.0f, a_wh = 0.0f, a_cls = 0.0f, a_n = 0.0f, a_conf = 0.0f;
    for (int t = threadIdx.x; t < NTG; t += blockDim.x) {
        if (!s_valid[t]) continue;
        int b = t / T;
        int gi = s_gi[t];
        const float* tg = tgt + (long)t * 5;
        const float* p = pred + ((long)b * HW + gi) * ROW;

        float cxW = tg[1] * fW, cyH = tg[2] * fH;
        float tx = cxW - floorf(cxW);
        float ty = cyH - floorf(cyH);
        float px = sigm(p[0]);
        float py = sigm(p[1]);
        a_xy += 0.5f * ((px - tx) * (px - tx) + (py - ty) * (py - ty));

        float pw = expf(p[2]);
        float ph = expf(p[3]);
        float tw = tg[3] * fW, th = tg[4] * fH;
        a_wh += 0.5f * ((pw - tw) * (pw - tw) + (ph - th) * (ph - th));

        int cid = (int)tg[0];
        float bce = 0.0f;
        #pragma unroll 4
        for (int c = 0; c < NCLS; c++) {
            float s = sigm(p[5 + c]);
            bce += (c == cid) ? -clog(s) : -clog(1.0f - s);
        }
        a_cls += bce * (1.0f / (float)NCLS);
        a_n += 1.0f;

        // first valid target in this batch mapping to this cell?
        bool first = true;
        for (int u = b * T; u < t; u++) {
            if (s_valid[u] && s_gi[u] == gi) { first = false; break; }
        }
        if (first) {
            float s = sigm(p[4]);
            a_conf += -clog(s) + clog(1.0f - s);  // swap (1-m) term for m term
        }
    }

    // ---- base conf sum from kernel 1 partials ----
    float a_base = 0.0f;
    for (int i = threadIdx.x; i < NB; i += blockDim.x) a_base += g_partials[i];

    // ---- deterministic block reductions ----
    float vals[6] = {a_xy, a_wh, a_cls, a_n, a_conf, a_base};
    float red[6];
    for (int k = 0; k < 6; k++) {
        sh[threadIdx.x] = vals[k];
        __syncthreads();
        for (int o = NT / 2; o > 0; o >>= 1) {
            if (threadIdx.x < o) sh[threadIdx.x] += sh[threadIdx.x + o];
            __syncthreads();
        }
        red[k] = sh[0];
        __syncthreads();
    }

    if (threadIdx.x == 0) {
        float denom = fmaxf(red[3], 1.0f);
        float loss_xy = red[0] / denom;
        float loss_wh = red[1] / denom;
        float loss_cls = red[2] / denom;
        float loss_conf = (red[5] + red[4]) / (float)((long)B * HW);
        float total = loss_xy * 5.0f + loss_wh * 5.0f + loss_conf + loss_cls;
        out[0] = total;
        out[1] = loss_xy;
        out[2] = loss_wh;
        out[3] = loss_conf;
        out[4] = loss_cls;
        for (int i = 5; i < out_size; i++) out[i] = 0.0f;
    }
}

extern "C" void kernel_launch(void* const* d_in, const int* in_sizes, int n_in,
                              void* d_out, int out_size) {
    const float* pred = (const float*)d_in[0];
    const float* tgt  = (const float*)d_in[1];
    const int* Hp = (const int*)d_in[2];
    const int* Wp = (const int*)d_in[3];
    long n_pred = in_sizes[0];
    long n_tgt  = in_sizes[1];
    long n_cells = n_pred / ROW;

    conf_base_kernel<<<NB, NT>>>(pred, n_cells);
    finish_kernel<<<1, NT>>>(pred, tgt, Hp, Wp, n_pred, n_tgt,
                             (float*)d_out, out_size);
}

// round 2
// speedup vs baseline: 10.4725x; 10.4725x over previous
#include <cuda_runtime.h>
#include <math.h>

#define ROW 85          // 5 + NUM_CLASSES
#define NCLS 80
#define DENSE_NB 512
#define NT 256
#define MAXT 8192       // max B*T supported
#define MAXTB 256       // max targets per batch cached in shared
#define LOG_CLAMP -100.0f

__device__ float g_dense[DENSE_NB];
__device__ float g_txy[MAXT];
__device__ float g_twh[MAXT];
__device__ float g_tcls[MAXT];
__device__ float g_tn[MAXT];
__device__ float g_tconf[MAXT];

__device__ __forceinline__ float sigm(float x) {
    return 1.0f / (1.0f + expf(-x));
}
// matches reference: max(log(s), -100); log(0) -> -inf -> -100
__device__ __forceinline__ float clog(float s) {
    return fmaxf(logf(s), LOG_CLAMP);
}
// decode H/W whether stored as int32 (or low word of int64) or float32 bits
__device__ __forceinline__ int decode_dim(const int* p) {
    int raw = p[0];
    if (raw >= (1 << 20) || raw < 0) return (int)__int_as_float(raw);
    return raw;
}

// target validity + cell index, identical math to the passing round-1 kernel
__device__ __forceinline__ void target_cell(const float* tg, float fW, float fH,
                                            int W, bool& valid, int& gi) {
    float cid = tg[0], cx = tg[1], cy = tg[2], w = tg[3], h = tg[4];
    bool fin = isfinite(cid) && isfinite(cx) && isfinite(cy) &&
               isfinite(w) && isfinite(h);
    float gx = floorf(cx * fW);
    float gy = floorf(cy * fH);
    valid = fin && (gx >= 0.0f) && (gx < fW) && (gy >= 0.0f) && (gy < fH);
    float gxc = fminf(fmaxf(gx, 0.0f), fW - 1.0f);
    float gyc = fminf(fmaxf(gy, 0.0f), fH - 1.0f);
    if (!(gxc == gxc)) gxc = 0.0f;
    if (!(gyc == gyc)) gyc = 0.0f;
    gi = (int)gyc * W + (int)gxc;
}

// Fused kernel:
//   blocks [0, DENSE_NB)          : dense conf BCE partial sums (obj_mask==0 case)
//   blocks [DENSE_NB, DENSE_NB+N) : one block per target -> gathered losses
__global__ void main_kernel(const float* __restrict__ pred,
                            const float* __restrict__ tgt,
                            const int* __restrict__ Hp,
                            const int* __restrict__ Wp,
                            long n_cells, int ntg) {
    __shared__ float sh[NT];

    if (blockIdx.x < DENSE_NB) {
        // ---------------- dense conf base ----------------
        float acc = 0.0f;
        for (long i = (long)blockIdx.x * NT + threadIdx.x; i < n_cells;
             i += (long)DENSE_NB * NT) {
            float x = __ldg(&pred[i * ROW + 4]);
            float s = sigm(x);
            acc += -clog(1.0f - s);
        }
        sh[threadIdx.x] = acc;
        __syncthreads();
        for (int o = NT / 2; o > 0; o >>= 1) {
            if (threadIdx.x < o) sh[threadIdx.x] += sh[threadIdx.x + o];
            __syncthreads();
        }
        if (threadIdx.x == 0) g_dense[blockIdx.x] = sh[0];
        return;
    }

    // ---------------- per-target block ----------------
    const int t = blockIdx.x - DENSE_NB;
    const int H = decode_dim(Hp);
    const int W = decode_dim(Wp);
    const long HW = (long)H * (long)W;
    const int B = (int)(n_cells / HW);
    const int T = ntg / B;
    const int b = t / T;
    const int tloc = t - b * T;
    const float fW = (float)W, fH = (float)H;

    __shared__ float s_b[MAXTB * 5];
    const float* bt;                       // batch targets (shared or global)
    if (T <= MAXTB) {
        const int nload = T * 5;
        const float* src = tgt + (long)b * nload;
        for (int i = threadIdx.x; i < nload; i += blockDim.x) s_b[i] = src[i];
        __syncthreads();
        bt = s_b;
    } else {
        bt = tgt + (long)b * T * 5;
    }

    const float* tg = bt + tloc * 5;
    bool valid;
    int gi;
    target_cell(tg, fW, fH, W, valid, gi);
    const float* p = pred + ((long)b * HW + gi) * ROW;

    // class BCE term: one thread per class (coalesced 320B row read)
    float v = 0.0f;
    if (valid && threadIdx.x < NCLS) {
        int cid = (int)tg[0];
        float s = sigm(__ldg(&p[5 + threadIdx.x]));
        v = ((int)threadIdx.x == cid) ? -clog(s) : -clog(1.0f - s);
    }
    sh[threadIdx.x] = v;
    __syncthreads();
    for (int o = NT / 2; o > 0; o >>= 1) {
        if (threadIdx.x < o) sh[threadIdx.x] += sh[threadIdx.x + o];
        __syncthreads();
    }

    if (threadIdx.x == 0) {
        float xy = 0.0f, wh = 0.0f, cf = 0.0f, n = 0.0f;
        if (valid) {
            float cxW = tg[1] * fW, cyH = tg[2] * fH;
            float tx = cxW - floorf(cxW);
            float ty = cyH - floorf(cyH);
            float px = sigm(p[0]);
            float py = sigm(p[1]);
            xy = 0.5f * ((px - tx) * (px - tx) + (py - ty) * (py - ty));

            float pw = expf(p[2]);
            float ph = expf(p[3]);
            float tw = tg[3] * fW, th = tg[4] * fH;
            wh = 0.5f * ((pw - tw) * (pw - tw) + (ph - th) * (ph - th));
            n = 1.0f;

            // conf correction only for the FIRST valid target hitting this cell
            bool first = true;
            for (int u = 0; u < tloc; u++) {
                bool vu; int gu;
                target_cell(bt + u * 5, fW, fH, W, vu, gu);
                if (vu && gu == gi) { first = false; break; }
            }
            if (first) {
                float s = sigm(p[4]);
                cf = -clog(s) + clog(1.0f - s);   // swap (1-m) term for m term
            }
        }
        g_txy[t] = xy;
        g_twh[t] = wh;
        g_tcls[t] = sh[0] * (1.0f / (float)NCLS);
        g_tn[t] = n;
        g_tconf[t] = cf;
    }
}

// Final single-block reduce + combine (deterministic fixed-order tree).
__global__ void reduce_kernel(long n_cells, int ntg,
                              float* __restrict__ out, int out_size) {
    __shared__ float sh[NT];
    float a[6] = {0, 0, 0, 0, 0, 0};
    for (int i = threadIdx.x; i < DENSE_NB; i += NT) a[5] += g_dense[i];
    for (int i = threadIdx.x; i < ntg; i += NT) {
        a[0] += g_txy[i];
        a[1] += g_twh[i];
        a[2] += g_tcls[i];
        a[3] += g_tn[i];
        a[4] += g_tconf[i];
    }
    float red[6];
    for (int k = 0; k < 6; k++) {
        sh[threadIdx.x] = a[k];
        __syncthreads();
        for (int o = NT / 2; o > 0; o >>= 1) {
            if (threadIdx.x < o) sh[threadIdx.x] += sh[threadIdx.x + o];
            __syncthreads();
        }
        red[k] = sh[0];
        __syncthreads();
    }
    if (threadIdx.x == 0) {
        float denom = fmaxf(red[3], 1.0f);
        float loss_xy = red[0] / denom;
        float loss_wh = red[1] / denom;
        float loss_cls = red[2] / denom;
        float loss_conf = (red[5] + red[4]) / (float)n_cells;
        float total = loss_xy * 5.0f + loss_wh * 5.0f + loss_conf + loss_cls;
        out[0] = total;
        out[1] = loss_xy;
        out[2] = loss_wh;
        out[3] = loss_conf;
        out[4] = loss_cls;
        for (int i = 5; i < out_size; i++) out[i] = 0.0f;
    }
}

extern "C" void kernel_launch(void* const* d_in, const int* in_sizes, int n_in,
                              void* d_out, int out_size) {
    const float* pred = (const float*)d_in[0];
    const float* tgt  = (const float*)d_in[1];
    const int* Hp = (const int*)d_in[2];
    const int* Wp = (const int*)d_in[3];
    long n_pred = in_sizes[0];
    long n_tgt  = in_sizes[1];
    long n_cells = n_pred / ROW;
    int ntg = (int)(n_tgt / 5);
    if (ntg > MAXT) ntg = MAXT;   // safety clamp (never expected to trigger)

    main_kernel<<<DENSE_NB + ntg, NT>>>(pred, tgt, Hp, Wp, n_cells, ntg);
    reduce_kernel<<<1, NT>>>(n_cells, ntg, (float*)d_out, out_size);
}